// round 5
// baseline (speedup 1.0000x reference)
#include <cuda_runtime.h>

// Problem constants
#define Bdim   8
#define Ndim   2048
#define Kdim   32
#define Fin    256
#define C2     512            // 2*F_OUT
#define MROWS  (Bdim * Ndim)  // 16384

// GEMM tile config
#define BM 128
#define BN 128
#define BK 16

#define STAT_BLOCKS 128

// --------- scratch (device globals: allocation-guard safe) ----------
__device__ float g_xneib[Bdim * Ndim * Fin];          // 16.8 MB
__device__ float g_part[STAT_BLOCKS * 1024];          // per-block (sum, sumsq) x 512 ch
__device__ float g_scale[C2];
__device__ float g_shift[C2];

// ====================================================================
// Kernel 1: neighbor gather + mean.  idx is shared across batch.
// One block per n; 512 threads = 8 batches x 64 float4 lanes.
// ====================================================================
__global__ void __launch_bounds__(512)
gather_mean_kernel(const float* __restrict__ x, const int* __restrict__ idx)
{
    __shared__ int sIdx[Kdim];
    const int n = blockIdx.x;
    if (threadIdx.x < Kdim) sIdx[threadIdx.x] = idx[n * Kdim + threadIdx.x];
    __syncthreads();

    const int b  = threadIdx.x >> 6;   // 0..7
    const int f4 = threadIdx.x & 63;   // 0..63 (float4 index within row)
    const float4* __restrict__ X4 = (const float4*)x;

    float4 acc = make_float4(0.f, 0.f, 0.f, 0.f);
#pragma unroll
    for (int k = 0; k < Kdim; k++) {
        const int j = sIdx[k];
        float4 v = X4[(((b << 11) + j) << 6) + f4];
        acc.x += v.x; acc.y += v.y; acc.z += v.z; acc.w += v.w;
    }
    const float s = 1.0f / (float)Kdim;
    acc.x *= s; acc.y *= s; acc.z *= s; acc.w *= s;
    ((float4*)g_xneib)[(((b << 11) + n) << 6) + f4] = acc;
}

// ====================================================================
// Kernel 2: dual GEMM.  H[r, 0:256]   = X      @ Wx^T + Wx_b
//                       H[r, 256:512] = x_neib @ Wn^T + Wn_b
// Grid: (MROWS/BM, 4).  blockIdx.y: 0,1 -> self half; 2,3 -> neighbor half.
// 128x128x16 tile, 256 threads, 8x8 microtile.
// ====================================================================
__global__ void __launch_bounds__(256)
gemm_kernel(const float* __restrict__ X,
            const float* __restrict__ Wx, const float* __restrict__ Wxb,
            const float* __restrict__ Wn, const float* __restrict__ Wnb,
            float* __restrict__ H)
{
    const int cb = blockIdx.y;
    const float* __restrict__ A    = (cb < 2) ? X   : g_xneib;
    const float* __restrict__ W    = (cb < 2) ? Wx  : Wn;
    const float* __restrict__ bias = (cb < 2) ? Wxb : Wnb;
    const int colBase    = (cb & 1) * BN;                    // within this GEMM's 256
    const int outColBase = ((cb < 2) ? 0 : 256) + colBase;   // within 512
    const int rowBase    = blockIdx.x * BM;

    __shared__ float As[BK][BM];
    __shared__ float Bs[BK][BN];

    const int tid = threadIdx.x;
    const int tx  = tid & 15;   // 0..15 -> 8 output cols each
    const int ty  = tid >> 4;   // 0..15 -> 8 output rows each

    float acc[8][8];
#pragma unroll
    for (int i = 0; i < 8; i++)
#pragma unroll
        for (int j = 0; j < 8; j++) acc[i][j] = 0.f;

    for (int k0 = 0; k0 < Fin; k0 += BK) {
        // Stage A tile (128 rows x 16 k) and W tile (128 outs x 16 k),
        // transposed into smem.  512 float4 each => 2 per thread.
#pragma unroll
        for (int t = 0; t < 2; t++) {
            const int li  = tid + 256 * t;
            const int row = li >> 2;       // 0..127
            const int kq  = li & 3;        // which float4 along k
            float4 va = *(const float4*)(A + (rowBase + row) * Fin + k0 + kq * 4);
            As[kq * 4 + 0][row] = va.x;
            As[kq * 4 + 1][row] = va.y;
            As[kq * 4 + 2][row] = va.z;
            As[kq * 4 + 3][row] = va.w;
            float4 vw = *(const float4*)(W + (colBase + row) * Fin + k0 + kq * 4);
            Bs[kq * 4 + 0][row] = vw.x;
            Bs[kq * 4 + 1][row] = vw.y;
            Bs[kq * 4 + 2][row] = vw.z;
            Bs[kq * 4 + 3][row] = vw.w;
        }
        __syncthreads();

#pragma unroll
        for (int kk = 0; kk < BK; kk++) {
            float a[8], b[8];
            *(float4*)&a[0] = *(const float4*)&As[kk][ty * 8];
            *(float4*)&a[4] = *(const float4*)&As[kk][ty * 8 + 4];
            *(float4*)&b[0] = *(const float4*)&Bs[kk][tx * 8];
            *(float4*)&b[4] = *(const float4*)&Bs[kk][tx * 8 + 4];
#pragma unroll
            for (int i = 0; i < 8; i++)
#pragma unroll
                for (int j = 0; j < 8; j++)
                    acc[i][j] += a[i] * b[j];
        }
        __syncthreads();
    }

    // Epilogue: add bias, write to H (row*512 + outCol)
#pragma unroll
    for (int i = 0; i < 8; i++) {
        const int row = rowBase + ty * 8 + i;
        float* out = H + row * C2 + outColBase + tx * 8;
        float4 r0, r1;
        r0.x = acc[i][0] + bias[colBase + tx * 8 + 0];
        r0.y = acc[i][1] + bias[colBase + tx * 8 + 1];
        r0.z = acc[i][2] + bias[colBase + tx * 8 + 2];
        r0.w = acc[i][3] + bias[colBase + tx * 8 + 3];
        r1.x = acc[i][4] + bias[colBase + tx * 8 + 4];
        r1.y = acc[i][5] + bias[colBase + tx * 8 + 5];
        r1.z = acc[i][6] + bias[colBase + tx * 8 + 6];
        r1.w = acc[i][7] + bias[colBase + tx * 8 + 7];
        *(float4*)(out)     = r0;
        *(float4*)(out + 4) = r1;
    }
}

// ====================================================================
// Kernel 3: per-row L2 normalize + ReLU (in place in H), and
// deterministic per-channel partial (sum, sumsq) for BatchNorm.
// 1 warp per row; each lane owns 16 fixed channels.
// Grid: STAT_BLOCKS x 256 threads (8 warps).
// ====================================================================
__global__ void __launch_bounds__(256)
norm_relu_stats_kernel(float* __restrict__ H)
{
    const int wid    = threadIdx.x >> 5;
    const int lane   = threadIdx.x & 31;
    const int gwarp  = blockIdx.x * 8 + wid;
    const int nwarps = gridDim.x * 8;

    float s[16], q[16];
#pragma unroll
    for (int i = 0; i < 16; i++) { s[i] = 0.f; q[i] = 0.f; }

    for (int r = gwarp; r < MROWS; r += nwarps) {
        float4* __restrict__ Hr = (float4*)(H + (size_t)r * C2);
        float4 v[4];
#pragma unroll
        for (int j = 0; j < 4; j++) v[j] = Hr[j * 32 + lane];

        float ss = 0.f;
#pragma unroll
        for (int j = 0; j < 4; j++)
            ss += v[j].x * v[j].x + v[j].y * v[j].y + v[j].z * v[j].z + v[j].w * v[j].w;
#pragma unroll
        for (int o = 16; o > 0; o >>= 1)
            ss += __shfl_xor_sync(0xffffffffu, ss, o);

        const float inv = 1.0f / fmaxf(sqrtf(ss), 1e-12f);
#pragma unroll
        for (int j = 0; j < 4; j++) {
            float4 u;
            u.x = fmaxf(v[j].x * inv, 0.f);
            u.y = fmaxf(v[j].y * inv, 0.f);
            u.z = fmaxf(v[j].z * inv, 0.f);
            u.w = fmaxf(v[j].w * inv, 0.f);
            Hr[j * 32 + lane] = u;
            s[j * 4 + 0] += u.x;  q[j * 4 + 0] += u.x * u.x;
            s[j * 4 + 1] += u.y;  q[j * 4 + 1] += u.y * u.y;
            s[j * 4 + 2] += u.z;  q[j * 4 + 2] += u.z * u.z;
            s[j * 4 + 3] += u.w;  q[j * 4 + 3] += u.w * u.w;
        }
    }

    // Deterministic block combine: each warp writes its partials, then a
    // fixed-order sum across the 8 warps.
    __shared__ float smS[8][C2];
    __shared__ float smQ[8][C2];
#pragma unroll
    for (int j = 0; j < 4; j++)
#pragma unroll
        for (int i = 0; i < 4; i++) {
            const int c = j * 128 + lane * 4 + i;
            smS[wid][c] = s[j * 4 + i];
            smQ[wid][c] = q[j * 4 + i];
        }
    __syncthreads();

    for (int c = threadIdx.x; c < C2; c += blockDim.x) {
        float S = 0.f, Q = 0.f;
#pragma unroll
        for (int w = 0; w < 8; w++) { S += smS[w][c]; Q += smQ[w][c]; }
        g_part[blockIdx.x * 1024 + c]       = S;
        g_part[blockIdx.x * 1024 + 512 + c] = Q;
    }
}

// ====================================================================
// Kernel 4: finalize BN stats -> per-channel scale/shift.  1 block, 512 thr.
// ====================================================================
__global__ void __launch_bounds__(512)
bn_finalize_kernel(const float* __restrict__ gamma, const float* __restrict__ beta)
{
    const int c = threadIdx.x;
    float S = 0.f, Q = 0.f;
    for (int b = 0; b < STAT_BLOCKS; b++) {
        S += g_part[b * 1024 + c];
        Q += g_part[b * 1024 + 512 + c];
    }
    const float invN = 1.0f / (float)MROWS;
    const float mean = S * invN;
    const float var  = Q * invN - mean * mean;
    const float sc   = gamma[c] * rsqrtf(var + 1e-5f);
    g_scale[c] = sc;
    g_shift[c] = beta[c] - mean * sc;
}

// ====================================================================
// Kernel 5: apply BN in place:  y = u*scale[c] + shift[c]
// ====================================================================
__global__ void __launch_bounds__(256)
bn_apply_kernel(float* __restrict__ H)
{
    __shared__ float4 ssc[C2 / 4];
    __shared__ float4 ssh[C2 / 4];
    for (int i = threadIdx.x; i < C2 / 4; i += blockDim.x) {
        ssc[i] = ((const float4*)g_scale)[i];
        ssh[i] = ((const float4*)g_shift)[i];
    }
    __syncthreads();

    const int total = MROWS * C2 / 4;   // float4 count
    float4* __restrict__ H4 = (float4*)H;
    for (int idx = blockIdx.x * blockDim.x + threadIdx.x; idx < total;
         idx += gridDim.x * blockDim.x) {
        const int c4 = idx & (C2 / 4 - 1);   // 128 float4 per row
        float4 v = H4[idx];
        const float4 sc = ssc[c4];
        const float4 sh = ssh[c4];
        v.x = v.x * sc.x + sh.x;
        v.y = v.y * sc.y + sh.y;
        v.z = v.z * sc.z + sh.z;
        v.w = v.w * sc.w + sh.w;
        H4[idx] = v;
    }
}

// ====================================================================
// Launch
// ====================================================================
extern "C" void kernel_launch(void* const* d_in, const int* in_sizes, int n_in,
                              void* d_out, int out_size)
{
    const float* x     = (const float*)d_in[0];
    const int*   idx   = (const int*)  d_in[1];
    const float* Wxw   = (const float*)d_in[2];
    const float* Wxb   = (const float*)d_in[3];
    const float* Wnw   = (const float*)d_in[4];
    const float* Wnb   = (const float*)d_in[5];
    const float* gamma = (const float*)d_in[6];
    const float* beta  = (const float*)d_in[7];
    float* H = (float*)d_out;

    gather_mean_kernel<<<Ndim, 512>>>(x, idx);

    dim3 ggrid(MROWS / BM, 4);
    gemm_kernel<<<ggrid, 256>>>(x, Wxw, Wxb, Wnw, Wnb, H);

    norm_relu_stats_kernel<<<STAT_BLOCKS, 256>>>(H);
    bn_finalize_kernel<<<1, 512>>>(gamma, beta);
    bn_apply_kernel<<<4096, 256>>>(H);
}

// round 6
// speedup vs baseline: 1.6109x; 1.6109x over previous
#include <cuda_runtime.h>
#include <cstdint>

// Problem constants
#define Bdim   8
#define Ndim   2048
#define Kdim   32
#define Fin    256
#define C2     512            // 2*F_OUT
#define MROWS  (Bdim * Ndim)  // 16384

// GEMM tile config (tf32 tensor-core path)
#define BM   128
#define BN   128
#define BK   16
#define BMP  132              // padded smem row stride (floats)

#define STAT_BLOCKS 128

// --------- scratch (device globals: allocation-guard safe) ----------
__device__ float g_xneib[Bdim * Ndim * Fin];          // 16.8 MB
__device__ float g_part[STAT_BLOCKS * 1024];          // per-block (sum, sumsq) x 512 ch
__device__ float g_scale[C2];
__device__ float g_shift[C2];

// ====================================================================
// Kernel 1: neighbor gather + mean.  idx is shared across batch.
// One block per n; 512 threads = 8 batches x 64 float4 lanes.
// ====================================================================
__global__ void __launch_bounds__(512)
gather_mean_kernel(const float* __restrict__ x, const int* __restrict__ idx)
{
    __shared__ int sIdx[Kdim];
    const int n = blockIdx.x;
    if (threadIdx.x < Kdim) sIdx[threadIdx.x] = idx[n * Kdim + threadIdx.x];
    __syncthreads();

    const int b  = threadIdx.x >> 6;   // 0..7
    const int f4 = threadIdx.x & 63;   // 0..63 (float4 index within row)
    const float4* __restrict__ X4 = (const float4*)x;

    float4 acc = make_float4(0.f, 0.f, 0.f, 0.f);
#pragma unroll
    for (int k = 0; k < Kdim; k++) {
        const int j = sIdx[k];
        float4 v = X4[(((b << 11) + j) << 6) + f4];
        acc.x += v.x; acc.y += v.y; acc.z += v.z; acc.w += v.w;
    }
    const float s = 1.0f / (float)Kdim;
    acc.x *= s; acc.y *= s; acc.z *= s; acc.w *= s;
    ((float4*)g_xneib)[(((b << 11) + n) << 6) + f4] = acc;
}

// ====================================================================
// tf32 helpers
// ====================================================================
__device__ __forceinline__ float to_tf32(float x) {
    float r;
    asm("cvt.rna.tf32.f32 %0, %1;" : "=f"(r) : "f"(x));
    return r;
}

__device__ __forceinline__ void mma_tf32(float* c, const uint32_t* a, const uint32_t* b) {
    asm volatile(
        "mma.sync.aligned.m16n8k8.row.col.f32.tf32.tf32.f32 "
        "{%0,%1,%2,%3}, {%4,%5,%6,%7}, {%8,%9}, {%0,%1,%2,%3};"
        : "+f"(c[0]), "+f"(c[1]), "+f"(c[2]), "+f"(c[3])
        : "r"(a[0]), "r"(a[1]), "r"(a[2]), "r"(a[3]),
          "r"(b[0]), "r"(b[1]));
}

// ====================================================================
// Kernel 2: dual GEMM via tf32 tensor cores.
//   H[r, 0:256]   = X      @ Wx^T + Wx_b
//   H[r, 256:512] = x_neib @ Wn^T + Wn_b
// Grid: (MROWS/BM, 4).  blockIdx.y: 0,1 -> self half; 2,3 -> neighbor half.
// 128x128 block tile, 256 threads, 8 warps (4x2) each 32x64, BK=16 double-buf.
// ====================================================================
__global__ void __launch_bounds__(256, 2)
gemm_tf32_kernel(const float* __restrict__ X,
                 const float* __restrict__ Wx, const float* __restrict__ Wxb,
                 const float* __restrict__ Wn, const float* __restrict__ Wnb,
                 float* __restrict__ H)
{
    const int cb = blockIdx.y;
    const float* __restrict__ A    = (cb < 2) ? X   : g_xneib;
    const float* __restrict__ W    = (cb < 2) ? Wx  : Wn;
    const float* __restrict__ bias = (cb < 2) ? Wxb : Wnb;
    const int colBase    = (cb & 1) * BN;                    // within this GEMM's 256
    const int outColBase = ((cb < 2) ? 0 : 256) + colBase;   // within 512
    const int rowBase    = blockIdx.x * BM;

    __shared__ float As[2][BK][BMP];
    __shared__ float Ws[2][BK][BMP];

    const int tid  = threadIdx.x;
    const int lane = tid & 31;
    const int warp = tid >> 5;
    const int wm = (warp & 3) * 32;   // warp row offset in tile
    const int wn = (warp >> 2) * 64;  // warp col offset in tile
    const int g  = lane >> 2;         // groupID 0..7
    const int t  = lane & 3;          // threadID-in-group 0..3

    float acc[2][8][4];
#pragma unroll
    for (int mt = 0; mt < 2; mt++)
#pragma unroll
        for (int nt = 0; nt < 8; nt++)
#pragma unroll
            for (int i = 0; i < 4; i++) acc[mt][nt][i] = 0.f;

    // Staging lambda-ish: each stage moves 128x16 of A and of W into smem
    // (2048 floats each = 512 float4; 256 threads -> 2 float4 per matrix).
    const int srow = tid >> 2;        // 0..63 base (with t-offset below)
    const int skq  = tid & 3;         // float4 index along k (0..3)

#define STAGE(buf, k0)                                                          \
    {                                                                           \
        _Pragma("unroll")                                                       \
        for (int tt = 0; tt < 2; tt++) {                                        \
            const int row = srow + 64 * tt;                                     \
            float4 va = *(const float4*)(A + (rowBase + row) * Fin + (k0) + skq * 4); \
            As[buf][skq * 4 + 0][row] = to_tf32(va.x);                          \
            As[buf][skq * 4 + 1][row] = to_tf32(va.y);                          \
            As[buf][skq * 4 + 2][row] = to_tf32(va.z);                          \
            As[buf][skq * 4 + 3][row] = to_tf32(va.w);                          \
            float4 vw = *(const float4*)(W + (colBase + row) * Fin + (k0) + skq * 4); \
            Ws[buf][skq * 4 + 0][row] = to_tf32(vw.x);                          \
            Ws[buf][skq * 4 + 1][row] = to_tf32(vw.y);                          \
            Ws[buf][skq * 4 + 2][row] = to_tf32(vw.z);                          \
            Ws[buf][skq * 4 + 3][row] = to_tf32(vw.w);                          \
        }                                                                       \
    }

    STAGE(0, 0);
    __syncthreads();

    const int NSTAGE = Fin / BK;  // 16
    for (int s = 0; s < NSTAGE; s++) {
        if (s + 1 < NSTAGE) STAGE((s + 1) & 1, (s + 1) * BK);
        const int buf = s & 1;

#pragma unroll
        for (int ks = 0; ks < 2; ks++) {
            const int k8 = ks * 8;
            uint32_t a[2][4];
#pragma unroll
            for (int mt = 0; mt < 2; mt++) {
                const int m0 = wm + mt * 16 + g;
                a[mt][0] = __float_as_uint(As[buf][k8 + t][m0]);
                a[mt][1] = __float_as_uint(As[buf][k8 + t][m0 + 8]);
                a[mt][2] = __float_as_uint(As[buf][k8 + t + 4][m0]);
                a[mt][3] = __float_as_uint(As[buf][k8 + t + 4][m0 + 8]);
            }
            uint32_t b[8][2];
#pragma unroll
            for (int nt = 0; nt < 8; nt++) {
                const int n0 = wn + nt * 8 + g;
                b[nt][0] = __float_as_uint(Ws[buf][k8 + t][n0]);
                b[nt][1] = __float_as_uint(Ws[buf][k8 + t + 4][n0]);
            }
#pragma unroll
            for (int mt = 0; mt < 2; mt++)
#pragma unroll
                for (int nt = 0; nt < 8; nt++)
                    mma_tf32(acc[mt][nt], a[mt], b[nt]);
        }
        __syncthreads();
    }
#undef STAGE

    // Epilogue: c0/c1 at (row=g, col=t*2, t*2+1), c2/c3 at row=g+8.
#pragma unroll
    for (int nt = 0; nt < 8; nt++) {
        const int c = wn + nt * 8 + t * 2;         // col within 128-tile
        const float b0 = bias[colBase + c];
        const float b1 = bias[colBase + c + 1];
#pragma unroll
        for (int mt = 0; mt < 2; mt++) {
            const int r0 = rowBase + wm + mt * 16 + g;
            float2 v0 = make_float2(acc[mt][nt][0] + b0, acc[mt][nt][1] + b1);
            float2 v1 = make_float2(acc[mt][nt][2] + b0, acc[mt][nt][3] + b1);
            *(float2*)(H + (size_t)r0 * C2 + outColBase + c)       = v0;
            *(float2*)(H + (size_t)(r0 + 8) * C2 + outColBase + c) = v1;
        }
    }
}

// ====================================================================
// Kernel 3: per-row L2 normalize + ReLU (in place in H), and
// deterministic per-channel partial (sum, sumsq) for BatchNorm.
// 1 warp per row; each lane owns 16 fixed channels.
// ====================================================================
__global__ void __launch_bounds__(256)
norm_relu_stats_kernel(float* __restrict__ H)
{
    const int wid    = threadIdx.x >> 5;
    const int lane   = threadIdx.x & 31;
    const int gwarp  = blockIdx.x * 8 + wid;
    const int nwarps = gridDim.x * 8;

    float s[16], q[16];
#pragma unroll
    for (int i = 0; i < 16; i++) { s[i] = 0.f; q[i] = 0.f; }

    for (int r = gwarp; r < MROWS; r += nwarps) {
        float4* __restrict__ Hr = (float4*)(H + (size_t)r * C2);
        float4 v[4];
#pragma unroll
        for (int j = 0; j < 4; j++) v[j] = Hr[j * 32 + lane];

        float ss = 0.f;
#pragma unroll
        for (int j = 0; j < 4; j++)
            ss += v[j].x * v[j].x + v[j].y * v[j].y + v[j].z * v[j].z + v[j].w * v[j].w;
#pragma unroll
        for (int o = 16; o > 0; o >>= 1)
            ss += __shfl_xor_sync(0xffffffffu, ss, o);

        const float inv = 1.0f / fmaxf(sqrtf(ss), 1e-12f);
#pragma unroll
        for (int j = 0; j < 4; j++) {
            float4 u;
            u.x = fmaxf(v[j].x * inv, 0.f);
            u.y = fmaxf(v[j].y * inv, 0.f);
            u.z = fmaxf(v[j].z * inv, 0.f);
            u.w = fmaxf(v[j].w * inv, 0.f);
            Hr[j * 32 + lane] = u;
            s[j * 4 + 0] += u.x;  q[j * 4 + 0] += u.x * u.x;
            s[j * 4 + 1] += u.y;  q[j * 4 + 1] += u.y * u.y;
            s[j * 4 + 2] += u.z;  q[j * 4 + 2] += u.z * u.z;
            s[j * 4 + 3] += u.w;  q[j * 4 + 3] += u.w * u.w;
        }
    }

    __shared__ float smS[8][C2];
    __shared__ float smQ[8][C2];
#pragma unroll
    for (int j = 0; j < 4; j++)
#pragma unroll
        for (int i = 0; i < 4; i++) {
            const int c = j * 128 + lane * 4 + i;
            smS[wid][c] = s[j * 4 + i];
            smQ[wid][c] = q[j * 4 + i];
        }
    __syncthreads();

    for (int c = threadIdx.x; c < C2; c += blockDim.x) {
        float S = 0.f, Q = 0.f;
#pragma unroll
        for (int w = 0; w < 8; w++) { S += smS[w][c]; Q += smQ[w][c]; }
        g_part[blockIdx.x * 1024 + c]       = S;
        g_part[blockIdx.x * 1024 + 512 + c] = Q;
    }
}

// ====================================================================
// Kernel 4: finalize BN stats -> per-channel scale/shift.
// Grid = C2 blocks (one per channel), 128 threads reduce 128 partials.
// ====================================================================
__global__ void __launch_bounds__(128)
bn_finalize_kernel(const float* __restrict__ gamma, const float* __restrict__ beta)
{
    const int c = blockIdx.x;
    const int t = threadIdx.x;
    float S = g_part[t * 1024 + c];
    float Q = g_part[t * 1024 + 512 + c];
#pragma unroll
    for (int o = 16; o > 0; o >>= 1) {
        S += __shfl_xor_sync(0xffffffffu, S, o);
        Q += __shfl_xor_sync(0xffffffffu, Q, o);
    }
    __shared__ float sS[4], sQ[4];
    if ((t & 31) == 0) { sS[t >> 5] = S; sQ[t >> 5] = Q; }
    __syncthreads();
    if (t == 0) {
        const float St = sS[0] + sS[1] + sS[2] + sS[3];
        const float Qt = sQ[0] + sQ[1] + sQ[2] + sQ[3];
        const float invN = 1.0f / (float)MROWS;
        const float mean = St * invN;
        const float var  = Qt * invN - mean * mean;
        const float sc   = gamma[c] * rsqrtf(var + 1e-5f);
        g_scale[c] = sc;
        g_shift[c] = beta[c] - mean * sc;
    }
}

// ====================================================================
// Kernel 5: apply BN in place:  y = u*scale[c] + shift[c]
// ====================================================================
__global__ void __launch_bounds__(256)
bn_apply_kernel(float* __restrict__ H)
{
    __shared__ float4 ssc[C2 / 4];
    __shared__ float4 ssh[C2 / 4];
    for (int i = threadIdx.x; i < C2 / 4; i += blockDim.x) {
        ssc[i] = ((const float4*)g_scale)[i];
        ssh[i] = ((const float4*)g_shift)[i];
    }
    __syncthreads();

    const int total = MROWS * C2 / 4;   // float4 count
    float4* __restrict__ H4 = (float4*)H;
    for (int idx = blockIdx.x * blockDim.x + threadIdx.x; idx < total;
         idx += gridDim.x * blockDim.x) {
        const int c4 = idx & (C2 / 4 - 1);   // 128 float4 per row
        float4 v = H4[idx];
        const float4 sc = ssc[c4];
        const float4 sh = ssh[c4];
        v.x = v.x * sc.x + sh.x;
        v.y = v.y * sc.y + sh.y;
        v.z = v.z * sc.z + sh.z;
        v.w = v.w * sc.w + sh.w;
        H4[idx] = v;
    }
}

// ====================================================================
// Launch
// ====================================================================
extern "C" void kernel_launch(void* const* d_in, const int* in_sizes, int n_in,
                              void* d_out, int out_size)
{
    const float* x     = (const float*)d_in[0];
    const int*   idx   = (const int*)  d_in[1];
    const float* Wxw   = (const float*)d_in[2];
    const float* Wxb   = (const float*)d_in[3];
    const float* Wnw   = (const float*)d_in[4];
    const float* Wnb   = (const float*)d_in[5];
    const float* gamma = (const float*)d_in[6];
    const float* beta  = (const float*)d_in[7];
    float* H = (float*)d_out;

    gather_mean_kernel<<<Ndim, 512>>>(x, idx);

    dim3 ggrid(MROWS / BM, 4);
    gemm_tf32_kernel<<<ggrid, 256>>>(x, Wxw, Wxb, Wnw, Wnb, H);

    norm_relu_stats_kernel<<<STAT_BLOCKS, 256>>>(H);
    bn_finalize_kernel<<<C2, 128>>>(gamma, beta);
    bn_apply_kernel<<<4096, 256>>>(H);
}

// round 14
// speedup vs baseline: 1.6769x; 1.0410x over previous
#include <cuda_runtime.h>
#include <cstdint>

// Problem constants
#define Bdim   8
#define Ndim   2048
#define Kdim   32
#define Fin    256
#define C2     512            // 2*F_OUT
#define MROWS  (Bdim * Ndim)  // 16384

// GEMM tile config (tf32 mma.sync path)
#define BM   128
#define BN   128
#define BK   16
#define BMP  132              // padded smem row stride (floats)

#define STAT_BLOCKS 128

// --------- scratch (device globals: allocation-guard safe) ----------
__device__ float g_xneib[MROWS * Fin];                // 16.8 MB
__device__ float g_partS[C2 * STAT_BLOCKS];           // transposed: [c][block]
__device__ float g_partQ[C2 * STAT_BLOCKS];
__device__ float g_scale[C2];
__device__ float g_shift[C2];

// ====================================================================
// tf32 helpers (Ampere-class mma.sync — the only tensor path that the
// harness's PTX target accepts; tcgen05 is rejected at ptxas)
// ====================================================================
__device__ __forceinline__ float to_tf32(float x) {
    float r;
    asm("cvt.rna.tf32.f32 %0, %1;" : "=f"(r) : "f"(x));
    return r;
}

__device__ __forceinline__ void mma_tf32(float* c, const uint32_t* a, const uint32_t* b) {
    asm volatile(
        "mma.sync.aligned.m16n8k8.row.col.f32.tf32.tf32.f32 "
        "{%0,%1,%2,%3}, {%4,%5,%6,%7}, {%8,%9}, {%0,%1,%2,%3};"
        : "+f"(c[0]), "+f"(c[1]), "+f"(c[2]), "+f"(c[3])
        : "r"(a[0]), "r"(a[1]), "r"(a[2]), "r"(a[3]),
          "r"(b[0]), "r"(b[1]));
}

// Shared-memory shapes for the two block roles in phase 1
struct SmemGemm {
    float As[2][BK][BMP];
    float Ws[2][BK][BMP];
};
union SmemPhase1 {
    SmemGemm g;
    int sIdx[Kdim];
};

// ====================================================================
// GEMM tile worker (from the proven R5 kernel): computes a 128x128 tile of
//   H[rowBase.., outColBase..] = A[rowBase..,:] @ W[colBase..,:]^T + bias
// 256 threads, 8 warps (4x2) each 32x64, BK=16 double-buffered.
// ====================================================================
__device__ __forceinline__ void gemm_tile(
    const float* __restrict__ A, const float* __restrict__ W,
    const float* __restrict__ bias,
    int rowBase, int colBase, int outColBase,
    float* __restrict__ H, SmemGemm* sm)
{
    const int tid  = threadIdx.x;
    const int lane = tid & 31;
    const int warp = tid >> 5;
    const int wm = (warp & 3) * 32;   // warp row offset in tile
    const int wn = (warp >> 2) * 64;  // warp col offset in tile
    const int g  = lane >> 2;         // groupID 0..7
    const int t  = lane & 3;          // threadID-in-group 0..3

    float acc[2][8][4];
#pragma unroll
    for (int mt = 0; mt < 2; mt++)
#pragma unroll
        for (int nt = 0; nt < 8; nt++)
#pragma unroll
            for (int i = 0; i < 4; i++) acc[mt][nt][i] = 0.f;

    const int srow = tid >> 2;        // 0..63 (+64 on second pass)
    const int skq  = tid & 3;         // float4 index along k (0..3)

#define STAGE(buf, k0)                                                          \
    {                                                                           \
        _Pragma("unroll")                                                       \
        for (int tt = 0; tt < 2; tt++) {                                        \
            const int row = srow + 64 * tt;                                     \
            float4 va = *(const float4*)(A + (size_t)(rowBase + row) * Fin + (k0) + skq * 4); \
            sm->As[buf][skq * 4 + 0][row] = to_tf32(va.x);                      \
            sm->As[buf][skq * 4 + 1][row] = to_tf32(va.y);                      \
            sm->As[buf][skq * 4 + 2][row] = to_tf32(va.z);                      \
            sm->As[buf][skq * 4 + 3][row] = to_tf32(va.w);                      \
            float4 vw = *(const float4*)(W + (size_t)(colBase + row) * Fin + (k0) + skq * 4); \
            sm->Ws[buf][skq * 4 + 0][row] = to_tf32(vw.x);                      \
            sm->Ws[buf][skq * 4 + 1][row] = to_tf32(vw.y);                      \
            sm->Ws[buf][skq * 4 + 2][row] = to_tf32(vw.z);                      \
            sm->Ws[buf][skq * 4 + 3][row] = to_tf32(vw.w);                      \
        }                                                                       \
    }

    STAGE(0, 0);
    __syncthreads();

    const int NSTAGE = Fin / BK;  // 16
    for (int s = 0; s < NSTAGE; s++) {
        if (s + 1 < NSTAGE) STAGE((s + 1) & 1, (s + 1) * BK);
        const int buf = s & 1;

#pragma unroll
        for (int ks = 0; ks < 2; ks++) {
            const int k8 = ks * 8;
            uint32_t a[2][4];
#pragma unroll
            for (int mt = 0; mt < 2; mt++) {
                const int m0 = wm + mt * 16 + g;
                a[mt][0] = __float_as_uint(sm->As[buf][k8 + t][m0]);
                a[mt][1] = __float_as_uint(sm->As[buf][k8 + t][m0 + 8]);
                a[mt][2] = __float_as_uint(sm->As[buf][k8 + t + 4][m0]);
                a[mt][3] = __float_as_uint(sm->As[buf][k8 + t + 4][m0 + 8]);
            }
            uint32_t b[8][2];
#pragma unroll
            for (int nt = 0; nt < 8; nt++) {
                const int n0 = wn + nt * 8 + g;
                b[nt][0] = __float_as_uint(sm->Ws[buf][k8 + t][n0]);
                b[nt][1] = __float_as_uint(sm->Ws[buf][k8 + t + 4][n0]);
            }
#pragma unroll
            for (int mt = 0; mt < 2; mt++)
#pragma unroll
                for (int nt = 0; nt < 8; nt++)
                    mma_tf32(acc[mt][nt], a[mt], b[nt]);
        }
        __syncthreads();
    }
#undef STAGE

    // Epilogue: c0/c1 at (row=g, col=t*2, t*2+1), c2/c3 at row=g+8.
#pragma unroll
    for (int nt = 0; nt < 8; nt++) {
        const int c = wn + nt * 8 + t * 2;         // col within 128-tile
        const float b0 = bias[colBase + c];
        const float b1 = bias[colBase + c + 1];
#pragma unroll
        for (int mt = 0; mt < 2; mt++) {
            const int r0 = rowBase + wm + mt * 16 + g;
            float2 v0 = make_float2(acc[mt][nt][0] + b0, acc[mt][nt][1] + b1);
            float2 v1 = make_float2(acc[mt][nt][2] + b0, acc[mt][nt][3] + b1);
            *(float2*)(H + (size_t)r0 * C2 + outColBase + c)       = v0;
            *(float2*)(H + (size_t)(r0 + 8) * C2 + outColBase + c) = v1;
        }
    }
}

// ====================================================================
// Phase 1: block-specialized launch.
//   blocks [0, 256):    self GEMM   H[:, 0:256] = X @ Wx^T + Wx_b
//   blocks [256, 2304): neighbor gather-mean -> g_xneib
// The gather's L2 stream overlaps the GEMM's tensor/FMA issue.
// ====================================================================
__global__ void __launch_bounds__(256, 2)
phase1_kernel(const float* __restrict__ x, const int* __restrict__ idx,
              const float* __restrict__ Wx, const float* __restrict__ Wxb,
              float* __restrict__ H)
{
    __shared__ SmemPhase1 sh;

    if (blockIdx.x < 256) {
        const int rowBase = (blockIdx.x >> 1) * BM;
        const int colBase = (blockIdx.x & 1) * BN;
        gemm_tile(x, Wx, Wxb, rowBase, colBase, colBase, H, &sh.g);
    } else {
        const int n = blockIdx.x - 256;          // 0..2047
        if (threadIdx.x < Kdim) sh.sIdx[threadIdx.x] = idx[n * Kdim + threadIdx.x];
        __syncthreads();

        const int b0 = threadIdx.x >> 6;          // 0..3
        const int f4 = threadIdx.x & 63;          // float4 lane within row
        const float4* __restrict__ X4 = (const float4*)x;
        const float s = 1.0f / (float)Kdim;

#pragma unroll
        for (int bb = 0; bb < 2; bb++) {
            const int b = b0 + bb * 4;            // 0..7
            float4 acc = make_float4(0.f, 0.f, 0.f, 0.f);
#pragma unroll
            for (int k = 0; k < Kdim; k++) {
                const int j = sh.sIdx[k];
                float4 v = X4[(((b << 11) + j) << 6) + f4];
                acc.x += v.x; acc.y += v.y; acc.z += v.z; acc.w += v.w;
            }
            acc.x *= s; acc.y *= s; acc.z *= s; acc.w *= s;
            ((float4*)g_xneib)[(((b << 11) + n) << 6) + f4] = acc;
        }
    }
}

// ====================================================================
// Phase 2: neighbor GEMM  H[:, 256:512] = xneib @ Wn^T + Wn_b
// ====================================================================
__global__ void __launch_bounds__(256, 2)
gemm_neib_kernel(const float* __restrict__ Wn, const float* __restrict__ Wnb,
                 float* __restrict__ H)
{
    __shared__ SmemGemm sh;
    const int rowBase = blockIdx.x * BM;
    const int colBase = blockIdx.y * BN;
    gemm_tile(g_xneib, Wn, Wnb, rowBase, colBase, 256 + colBase, H, &sh);
}

// ====================================================================
// Kernel 3: per-row L2 normalize + ReLU (in place), per-channel partials.
// ====================================================================
__global__ void __launch_bounds__(256)
norm_relu_stats_kernel(float* __restrict__ H)
{
    const int wid    = threadIdx.x >> 5;
    const int lane   = threadIdx.x & 31;
    const int gwarp  = blockIdx.x * 8 + wid;
    const int nwarps = gridDim.x * 8;

    float s[16], q[16];
#pragma unroll
    for (int i = 0; i < 16; i++) { s[i] = 0.f; q[i] = 0.f; }

    for (int r = gwarp; r < MROWS; r += nwarps) {
        float4* __restrict__ Hr = (float4*)(H + (size_t)r * C2);
        float4 v[4];
#pragma unroll
        for (int j = 0; j < 4; j++) v[j] = Hr[j * 32 + lane];

        float ss = 0.f;
#pragma unroll
        for (int j = 0; j < 4; j++)
            ss += v[j].x * v[j].x + v[j].y * v[j].y + v[j].z * v[j].z + v[j].w * v[j].w;
#pragma unroll
        for (int o = 16; o > 0; o >>= 1)
            ss += __shfl_xor_sync(0xffffffffu, ss, o);

        const float inv = 1.0f / fmaxf(sqrtf(ss), 1e-12f);
#pragma unroll
        for (int j = 0; j < 4; j++) {
            float4 u;
            u.x = fmaxf(v[j].x * inv, 0.f);
            u.y = fmaxf(v[j].y * inv, 0.f);
            u.z = fmaxf(v[j].z * inv, 0.f);
            u.w = fmaxf(v[j].w * inv, 0.f);
            Hr[j * 32 + lane] = u;
            s[j * 4 + 0] += u.x;  q[j * 4 + 0] += u.x * u.x;
            s[j * 4 + 1] += u.y;  q[j * 4 + 1] += u.y * u.y;
            s[j * 4 + 2] += u.z;  q[j * 4 + 2] += u.z * u.z;
            s[j * 4 + 3] += u.w;  q[j * 4 + 3] += u.w * u.w;
        }
    }

    __shared__ float smS[8][C2];
    __shared__ float smQ[8][C2];
#pragma unroll
    for (int j = 0; j < 4; j++)
#pragma unroll
        for (int i = 0; i < 4; i++) {
            const int c = j * 128 + lane * 4 + i;
            smS[wid][c] = s[j * 4 + i];
            smQ[wid][c] = q[j * 4 + i];
        }
    __syncthreads();

    for (int c = threadIdx.x; c < C2; c += blockDim.x) {
        float S = 0.f, Q = 0.f;
#pragma unroll
        for (int w = 0; w < 8; w++) { S += smS[w][c]; Q += smQ[w][c]; }
        g_partS[c * STAT_BLOCKS + blockIdx.x] = S;   // transposed for finalize
        g_partQ[c * STAT_BLOCKS + blockIdx.x] = Q;
    }
}

// ====================================================================
// Kernel 4: finalize BN stats. 16 blocks x 256 threads; one warp per
// 4 channels, coalesced float4 reads of the transposed partials.
// ====================================================================
__global__ void __launch_bounds__(256)
bn_finalize_kernel(const float* __restrict__ gamma, const float* __restrict__ beta)
{
    const int gw   = (blockIdx.x * 256 + threadIdx.x) >> 5;  // 0..127
    const int lane = threadIdx.x & 31;
#pragma unroll
    for (int ci = 0; ci < 4; ci++) {
        const int c = gw * 4 + ci;
        float4 s4 = *(const float4*)&g_partS[c * STAT_BLOCKS + lane * 4];
        float4 q4 = *(const float4*)&g_partQ[c * STAT_BLOCKS + lane * 4];
        float S = s4.x + s4.y + s4.z + s4.w;
        float Q = q4.x + q4.y + q4.z + q4.w;
#pragma unroll
        for (int o = 16; o > 0; o >>= 1) {
            S += __shfl_xor_sync(0xffffffffu, S, o);
            Q += __shfl_xor_sync(0xffffffffu, Q, o);
        }
        if (lane == 0) {
            const float invN = 1.0f / (float)MROWS;
            const float mean = S * invN;
            const float var  = Q * invN - mean * mean;
            const float sc   = gamma[c] * rsqrtf(var + 1e-5f);
            g_scale[c] = sc;
            g_shift[c] = beta[c] - mean * sc;
        }
    }
}

// ====================================================================
// Kernel 5: apply BN in place:  y = u*scale[c] + shift[c]
// ====================================================================
__global__ void __launch_bounds__(256)
bn_apply_kernel(float* __restrict__ H)
{
    __shared__ float4 ssc[C2 / 4];
    __shared__ float4 ssh[C2 / 4];
    for (int i = threadIdx.x; i < C2 / 4; i += blockDim.x) {
        ssc[i] = ((const float4*)g_scale)[i];
        ssh[i] = ((const float4*)g_shift)[i];
    }
    __syncthreads();

    const int total = MROWS * C2 / 4;
    float4* __restrict__ H4 = (float4*)H;
    for (int idx = blockIdx.x * blockDim.x + threadIdx.x; idx < total;
         idx += gridDim.x * blockDim.x) {
        const int c4 = idx & (C2 / 4 - 1);
        float4 v = H4[idx];
        const float4 sc = ssc[c4];
        const float4 sh = ssh[c4];
        v.x = v.x * sc.x + sh.x;
        v.y = v.y * sc.y + sh.y;
        v.z = v.z * sc.z + sh.z;
        v.w = v.w * sc.w + sh.w;
        H4[idx] = v;
    }
}

// ====================================================================
// Launch
// ====================================================================
extern "C" void kernel_launch(void* const* d_in, const int* in_sizes, int n_in,
                              void* d_out, int out_size)
{
    const float* x     = (const float*)d_in[0];
    const int*   idx   = (const int*)  d_in[1];
    const float* Wxw   = (const float*)d_in[2];
    const float* Wxb   = (const float*)d_in[3];
    const float* Wnw   = (const float*)d_in[4];
    const float* Wnb   = (const float*)d_in[5];
    const float* gamma = (const float*)d_in[6];
    const float* beta  = (const float*)d_in[7];
    float* H = (float*)d_out;

    // Phase 1: self GEMM (256 blocks) + neighbor gather (2048 blocks), one launch
    phase1_kernel<<<256 + Ndim, 256>>>(x, idx, Wxw, Wxb, H);

    // Phase 2: neighbor GEMM
    dim3 ngrid(MROWS / BM, 2);
    gemm_neib_kernel<<<ngrid, 256>>>(Wnw, Wnb, H);

    norm_relu_stats_kernel<<<STAT_BLOCKS, 256>>>(H);
    bn_finalize_kernel<<<16, 256>>>(gamma, beta);
    bn_apply_kernel<<<4096, 256>>>(H);
}